// round 5
// baseline (speedup 1.0000x reference)
#include <cuda_runtime.h>
#include <math.h>

#define Dn   512
#define FDn  2048
#define On   256
#define Kn   49
#define Bn   4
#define Cn   256
#define Hn   64
#define Wn   48
#define HWn  3072
#define Nn   32
#define KOn  (Kn*On)   // 12544
#define VSPLIT 16
#define BSPLIT 4

typedef unsigned long long u64;

__device__ float  g_eps [Nn*FDn];
__device__ float  g_v   [Nn*Dn];
__device__ float  g_bvp [BSPLIT*Nn*KOn];
__device__ float  g_A   [Hn*On];
__device__ float  g_Bm  [Wn*On];
__device__ float  g_eGA [Nn*Kn*Hn];
__device__ float  g_eGB [Nn*Kn*Wn];
__device__ float  g_eapp[Bn*Kn*HWn];
__device__ double g_invden[512];

__device__ __forceinline__ void ffma2(u64 &acc, u64 a, u64 b) {
    asm volatile("fma.rn.f32x2 %0, %1, %2, %0;" : "+l"(acc) : "l"(a), "l"(b));
}
__device__ __forceinline__ float hsum2(u64 a) {
    float2 f = *reinterpret_cast<float2*>(&a);
    return f.x + f.y;
}

// ---------------- init: invden table (exp2, no pow) + zero g_v ----------------
__global__ void k_init() {
    int t = blockIdx.x*256 + threadIdx.x;   // grid 8 -> 2048 threads
    if (t < 512) {
        double e = (t < 256) ? (2.0*t + 1.0)/512.0 : (2.0*(t-256))/512.0;
        g_invden[t] = exp2(-e * 9.9657842846620870436);  // log2(1000)
    }
    for (int i = t; i < Nn*Dn; i += 2048) g_v[i] = 0.0f;
}

// accurate & cheap: double range-reduction, float trig on [-pi,pi]
__device__ __forceinline__ float embed_val(float z, int dd) {
    double a = (double)z * g_invden[dd];
    double k = rint(a * 0.15915494309189535);           // 1/(2*pi)
    float  r = (float)(a - k * 6.2831853071795864769);
    return (dd < 256) ? sinf(r) : cosf(r);
}

// ---------------- fused: eps (0..31) | A/B (32..143) ----------------
__global__ void k_pre(const float* __restrict__ rois,
                      const float* __restrict__ W_im) {
    int bid = blockIdx.x;
    if (bid < Nn) {
        int n = bid;
        float c0 = rois[n*5+1], c1 = rois[n*5+2], c2 = rois[n*5+3], c3 = rois[n*5+4];
        for (int i = threadIdx.x; i < FDn; i += blockDim.x) {
            int c  = i >> 9;
            int dd = i & 511;
            float z = (c >= 2) ? ((c == 3) ? c3 : c2) : ((c == 1) ? c1 : c0);
            g_eps[n*FDn + i] = embed_val(z, dd);
        }
    } else {
        __shared__ __align__(16) float pe[Dn];
        int j = bid - Nn;
        bool isA = (j < Hn);
        float z = (float)(isA ? j : (j - Hn));
        for (int dd = threadIdx.x; dd < Dn; dd += blockDim.x)
            pe[dd] = embed_val(z, dd);
        __syncthreads();
        int o = threadIdx.x;
        const ulonglong2* w2 = (const ulonglong2*)(W_im + (size_t)o * (2*Dn) + (isA ? 0 : Dn));
        const ulonglong2* p2 = (const ulonglong2*)pe;
        u64 acc = 0;
        #pragma unroll 8
        for (int f = 0; f < Dn/4; ++f) {
            ulonglong2 wv = w2[f], pv = p2[f];
            ffma2(acc, wv.x, pv.x);
            ffma2(acc, wv.y, pv.y);
        }
        if (isA) g_A[j*On + o] = hsum2(acc);
        else     g_Bm[(j-Hn)*On + o] = hsum2(acc);
    }
}

// ---------------- v: grid (8 d-tiles, 16 f-slices), atomic reduce ----------------
__global__ void k_v(const float* __restrict__ V_box) {
    __shared__ __align__(16) float eps_s[Nn*128]; // 16 KB
    int dp = blockIdx.x, ks = blockIdx.y;
    int f0 = ks * 128;
    for (int i = threadIdx.x; i < Nn*128; i += 256) {
        int n = i >> 7, f = i & 127;
        eps_s[i] = g_eps[n*FDn + f0 + f];
    }
    __syncthreads();
    int dl = threadIdx.x & 63, ng = threadIdx.x >> 6;
    int d  = dp*64 + dl, n0 = ng*8;
    const ulonglong2* vb = (const ulonglong2*)(V_box + (size_t)d*FDn + f0);
    u64 acc[8] = {0,0,0,0,0,0,0,0};
    #pragma unroll 8
    for (int f = 0; f < 32; ++f) {
        ulonglong2 wv = vb[f];
        #pragma unroll
        for (int j = 0; j < 8; ++j) {
            ulonglong2 vv = *(const ulonglong2*)(eps_s + (n0+j)*128 + f*4);
            ffma2(acc[j], wv.x, vv.x);
            ffma2(acc[j], wv.y, vv.y);
        }
    }
    #pragma unroll
    for (int j = 0; j < 8; ++j)
        atomicAdd(&g_v[(size_t)(n0+j)*Dn + d], hsum2(acc[j]));
}

// ---------------- bvec partials: grid (196 ko-tiles, 4 d-slices) ----------------
__global__ void k_bvec(const float* __restrict__ W_box) {
    __shared__ __align__(16) float v_s[Nn*128]; // 16 KB
    int ks = blockIdx.y;
    int f0 = ks * 128;
    for (int i = threadIdx.x; i < Nn*128; i += 256) {
        int n = i >> 7, fl = i & 127;
        v_s[i] = g_v[n*Dn + f0 + fl];
    }
    __syncthreads();
    int kol = threadIdx.x & 63;
    int ng  = threadIdx.x >> 6;
    int n0  = ng * 8;
    int ko  = blockIdx.x * 64 + kol;
    const ulonglong2* wb = (const ulonglong2*)(W_box + (size_t)ko * Dn + f0);
    u64 acc[8] = {0,0,0,0,0,0,0,0};
    #pragma unroll 8
    for (int f = 0; f < 32; ++f) {
        ulonglong2 wv = wb[f];
        #pragma unroll
        for (int j = 0; j < 8; ++j) {
            ulonglong2 vv = *(const ulonglong2*)(v_s + (n0+j)*128 + f*4);
            ffma2(acc[j], wv.x, vv.x);
            ffma2(acc[j], wv.y, vv.y);
        }
    }
    #pragma unroll
    for (int j = 0; j < 8; ++j)
        g_bvp[(size_t)ks*(Nn*KOn) + (size_t)(n0+j)*KOn + ko] = hsum2(acc[j]);
}

// ---------------- eGA/eGB: grid (n, side, 7 k-groups) ----------------
__global__ void k_GAB() {
    extern __shared__ __align__(16) float sm[];
    float* bv_s = sm;         // 7*256
    float* M_s  = sm + 7*256; // 256*(L+1)
    int n  = blockIdx.x;
    bool isA = (blockIdx.y == 0);
    int kg = blockIdx.z;
    int k0 = kg * 7;
    int L  = isA ? Hn : Wn;
    int Lp = L + 1;
    const float* src = isA ? g_A : g_Bm;
    for (int i = threadIdx.x; i < 7*256; i += 256) {
        size_t base = (size_t)n*KOn + (size_t)k0*256 + i;
        float s = 0.f;
        #pragma unroll
        for (int p = 0; p < BSPLIT; ++p) s += g_bvp[(size_t)p*(Nn*KOn) + base];
        bv_s[i] = s;
    }
    for (int i = threadIdx.x; i < L*On; i += 256) {
        int l = i / On, o = i & 255;
        M_s[o*Lp + l] = src[i];
    }
    __syncthreads();
    float* dst = isA ? (g_eGA + n*Kn*Hn) : (g_eGB + n*Kn*Wn);
    if (isA) {
        for (int idx = threadIdx.x; idx < 7*Hn; idx += 256) {
            int kk = idx >> 6, l = idx & 63;
            const float4* bp = (const float4*)(bv_s + kk*256);
            float acc = 0.f;
            #pragma unroll 8
            for (int o4 = 0; o4 < 64; ++o4) {
                float4 bv = bp[o4];
                int ob = o4*4;
                acc += bv.x*M_s[ ob   *65 + l] + bv.y*M_s[(ob+1)*65 + l]
                     + bv.z*M_s[(ob+2)*65 + l] + bv.w*M_s[(ob+3)*65 + l];
            }
            dst[(k0+kk)*Hn + l] = expf(acc);
        }
    } else {
        for (int idx = threadIdx.x; idx < 7*Wn; idx += 256) {
            int kk = idx / 48, l = idx - kk*48;
            const float4* bp = (const float4*)(bv_s + kk*256);
            float acc = 0.f;
            #pragma unroll 8
            for (int o4 = 0; o4 < 64; ++o4) {
                float4 bv = bp[o4];
                int ob = o4*4;
                acc += bv.x*M_s[ ob   *49 + l] + bv.y*M_s[(ob+1)*49 + l]
                     + bv.z*M_s[(ob+2)*49 + l] + bv.w*M_s[(ob+3)*49 + l];
            }
            dst[(k0+kk)*Wn + l] = expf(acc);
        }
    }
}

// ---------------- eapp fused: grid (48 px-tiles, B), 128 thr, all 256 C ----------
__global__ void k_app(const float* __restrict__ x,
                      const float* __restrict__ conv_w,
                      const float* __restrict__ conv_b) {
    extern __shared__ __align__(16) float sm2[];
    float* cw_s = sm2;             // 56*256 = 57 KB
    float* x_s  = sm2 + 56*256;    // 64*64  = 16 KB
    int b   = blockIdx.y;
    int px0 = blockIdx.x * 64;
    for (int i = threadIdx.x; i < 56*256; i += 128) {
        int k = i >> 8, c = i & 255;
        cw_s[i] = (k < Kn) ? conv_w[k*Cn + c] : 0.0f;
    }
    int lane = threadIdx.x & 15;   // 4 px each
    int kg   = threadIdx.x >> 4;   // 8 groups x 7 k
    int k0   = kg * 7;
    u64 acc[7][2];
    #pragma unroll
    for (int kk = 0; kk < 7; ++kk) { acc[kk][0] = 0; acc[kk][1] = 0; }

    for (int c0 = 0; c0 < Cn; c0 += 64) {
        __syncthreads();
        for (int i = threadIdx.x; i < 64*64; i += 128) {
            int c = i >> 6, p = i & 63;
            x_s[i] = x[((size_t)b*Cn + c0 + c)*HWn + px0 + p];
        }
        __syncthreads();
        #pragma unroll 4
        for (int c = 0; c < 64; ++c) {
            ulonglong2 xv = *(const ulonglong2*)(x_s + c*64 + lane*4);
            #pragma unroll
            for (int kk = 0; kk < 7; ++kk) {
                float w = cw_s[(k0+kk)*256 + c0 + c];
                u64 w2; asm("mov.b64 %0, {%1, %1};" : "=l"(w2) : "f"(w));
                ffma2(acc[kk][0], w2, xv.x);
                ffma2(acc[kk][1], w2, xv.y);
            }
        }
    }
    int p0 = px0 + lane*4;
    #pragma unroll
    for (int kk = 0; kk < 7; ++kk) {
        int k = k0 + kk;
        if (k < Kn) {
            float bias = conv_b[k];
            float2 a0 = *(float2*)&acc[kk][0];
            float2 a1 = *(float2*)&acc[kk][1];
            float4 v;
            v.x = expf(a0.x + bias);
            v.y = expf(a0.y + bias);
            v.z = expf(a1.x + bias);
            v.w = expf(a1.y + bias);
            *(float4*)(g_eapp + ((size_t)b*Kn + k)*HWn + p0) = v;
        }
    }
}

// ---------------- final: softmax over k, permuted write (inline rank) ----------
__global__ void k_final(const float* __restrict__ rois, float* __restrict__ out) {
    __shared__ float eGA_s[Kn*Hn];
    __shared__ float eGB_s[Kn*Wn];
    __shared__ int r_s;
    int nb = blockIdx.y;
    int n = nb >> 2, b = nb & 3;
    if (threadIdx.x == 0) {
        int my = (int)rois[n*5];
        int r = 0;
        #pragma unroll
        for (int j = 0; j < Nn; ++j) {
            int o = (int)rois[j*5];
            r += (o < my) || (o == my && j < n);
        }
        r_s = r;
    }
    for (int i = threadIdx.x; i < Kn*Hn; i += 256) eGA_s[i] = g_eGA[n*Kn*Hn + i];
    for (int i = threadIdx.x; i < Kn*Wn; i += 256) eGB_s[i] = g_eGB[n*Kn*Wn + i];
    __syncthreads();
    int p = blockIdx.x*256 + threadIdx.x;
    int h = p / 48;
    int w = p - h*48;
    const float* ea = g_eapp + (size_t)b*Kn*HWn + p;
    float pr[Kn];
    float s = 0.f;
    #pragma unroll
    for (int k = 0; k < Kn; ++k) {
        pr[k] = eGA_s[k*Hn + h] * eGB_s[k*Wn + w] * ea[(size_t)k*HWn];
        s += pr[k];
    }
    float inv = 1.0f / s;
    float* op = out + ((size_t)(r_s*Bn + b)*Kn)*HWn + p;
    #pragma unroll
    for (int k = 0; k < Kn; ++k)
        op[(size_t)k*HWn] = pr[k] * inv;
}

extern "C" void kernel_launch(void* const* d_in, const int* in_sizes, int n_in,
                              void* d_out, int out_size) {
    const float* x      = (const float*)d_in[0];
    const float* rois   = (const float*)d_in[1];
    const float* V_box  = (const float*)d_in[2];
    const float* W_box  = (const float*)d_in[3];
    const float* W_im   = (const float*)d_in[4];
    const float* conv_w = (const float*)d_in[5];
    const float* conv_b = (const float*)d_in[6];
    float* out = (float*)d_out;

    cudaFuncSetAttribute(k_GAB, cudaFuncAttributeMaxDynamicSharedMemorySize,
                         (7*256 + 256*65) * 4);
    cudaFuncSetAttribute(k_app, cudaFuncAttributeMaxDynamicSharedMemorySize,
                         (56*256 + 64*64) * 4);

    k_init <<<8, 256>>>();
    k_pre  <<<Nn + Hn + Wn, 256>>>(rois, W_im);
    k_app  <<<dim3(HWn/64, Bn), 128, (56*256 + 64*64)*4>>>(x, conv_w, conv_b);
    k_v    <<<dim3(8, VSPLIT), 256>>>(V_box);
    k_bvec <<<dim3(KOn/64, BSPLIT), 256>>>(W_box);
    k_GAB  <<<dim3(Nn, 2, 7), 256, (7*256 + 256*65)*4>>>();
    k_final<<<dim3(HWn/256, Nn*Bn), 256>>>(rois, out);
}

// round 6
// speedup vs baseline: 1.3112x; 1.3112x over previous
#include <cuda_runtime.h>
#include <math.h>

#define Dn   512
#define FDn  2048
#define On   256
#define Kn   49
#define Bn   4
#define Cn   256
#define Hn   64
#define Wn   48
#define HWn  3072
#define Nn   32
#define KOn  (Kn*On)   // 12544
#define BSPLIT 4

typedef unsigned long long u64;

__device__ float g_eps [Nn*FDn];
__device__ float g_v   [Nn*Dn];
__device__ float g_bvp [BSPLIT*Nn*KOn];
__device__ float g_A   [Hn*On];
__device__ float g_Bm  [Wn*On];
__device__ float g_eGA [Nn*Kn*Hn];
__device__ float g_eGB [Nn*Kn*Wn];
__device__ float g_eapp[Bn*Kn*HWn];

__device__ __forceinline__ void ffma2(u64 &acc, u64 a, u64 b) {
    asm volatile("fma.rn.f32x2 %0, %1, %2, %0;" : "+l"(acc) : "l"(a), "l"(b));
}
__device__ __forceinline__ float hsum2(u64 a) {
    float2 f = *reinterpret_cast<float2*>(&a);
    return f.x + f.y;
}

// cheap & accurate: float table value, double range-reduction, float trig
__device__ __forceinline__ float embed_val(float z, int dd) {
    float e = (dd < 256) ? (2.0f*dd + 1.0f)*(1.0f/512.0f) : (2.0f*(dd-256))*(1.0f/512.0f);
    float invden = exp2f(-e * 9.96578428466209f);   // 1000^-e
    double a = (double)z * (double)invden;
    double k = rint(a * 0.15915494309189535);
    float  r = (float)(a - k * 6.2831853071795864769);
    return (dd < 256) ? sinf(r) : cosf(r);
}

// ---------------- fused: eps (0..31) | A/B (32..143) | zero g_v (144..145) ----
__global__ void k_pre(const float* __restrict__ rois,
                      const float* __restrict__ W_im) {
    int bid = blockIdx.x;
    if (bid < Nn) {
        int n = bid;
        float c0 = rois[n*5+1], c1 = rois[n*5+2], c2 = rois[n*5+3], c3 = rois[n*5+4];
        for (int i = threadIdx.x; i < FDn; i += blockDim.x) {
            int c  = i >> 9;
            int dd = i & 511;
            float z = (c >= 2) ? ((c == 3) ? c3 : c2) : ((c == 1) ? c1 : c0);
            g_eps[n*FDn + i] = embed_val(z, dd);
        }
    } else if (bid < Nn + Hn + Wn) {
        __shared__ __align__(16) float pe[Dn];
        int j = bid - Nn;
        bool isA = (j < Hn);
        float z = (float)(isA ? j : (j - Hn));
        for (int dd = threadIdx.x; dd < Dn; dd += blockDim.x)
            pe[dd] = embed_val(z, dd);
        __syncthreads();
        int o = threadIdx.x;
        const ulonglong2* w2 = (const ulonglong2*)(W_im + (size_t)o * (2*Dn) + (isA ? 0 : Dn));
        const ulonglong2* p2 = (const ulonglong2*)pe;
        u64 acc = 0;
        #pragma unroll 8
        for (int f = 0; f < Dn/4; ++f) {
            ulonglong2 wv = w2[f], pv = p2[f];
            ffma2(acc, wv.x, pv.x);
            ffma2(acc, wv.y, pv.y);
        }
        if (isA) g_A[j*On + o] = hsum2(acc);
        else     g_Bm[(j-Hn)*On + o] = hsum2(acc);
    } else {
        int half = bid - (Nn + Hn + Wn);        // 0 or 1
        int base = half * (Nn*Dn/2);
        for (int i = threadIdx.x; i < Nn*Dn/2; i += 256)
            g_v[base + i] = 0.0f;
    }
}

// ================= fused v (blocks 0..255) + app (blocks 256..447) =============
// v: grid 16 dp x 16 ks; smem-staged V tile (coalesced), atomic reduce into g_v
// app: 48 px-tiles x 4 b; eapp = exp(conv + bias)
__global__ void k_vapp(const float* __restrict__ V_box,
                       const float* __restrict__ x,
                       const float* __restrict__ conv_w,
                       const float* __restrict__ conv_b) {
    extern __shared__ __align__(16) float sm[];
    int bx = blockIdx.x;
    if (bx < 256) {
        // ---------------- v role ----------------
        float* eps_s = sm;             // [32 n][128 f]
        float* vt_s  = sm + 32*128;    // [32 d][130]  (pad 2)
        int dp = bx >> 4, ks = bx & 15;
        int f0 = ks * 128;
        for (int i = threadIdx.x; i < 32*128; i += 256) {
            int n = i >> 7, f = i & 127;
            eps_s[i] = g_eps[n*FDn + f0 + f];
        }
        // stage V tile: 32 d rows x 128 f, coalesced (f fast)
        int srow = threadIdx.x >> 5, scol = threadIdx.x & 31;
        #pragma unroll
        for (int p = 0; p < 4; ++p) {
            int row = p*8 + srow;
            float4 vv = *(const float4*)(V_box + (size_t)(dp*32 + row)*FDn + f0 + scol*4);
            float* dst = vt_s + row*130 + scol*4;
            *(float2*)(dst)     = make_float2(vv.x, vv.y);
            *(float2*)(dst + 2) = make_float2(vv.z, vv.w);
        }
        __syncthreads();
        int dl = threadIdx.x & 31, ng = threadIdx.x >> 5;
        int d  = dp*32 + dl, n0 = ng*4;
        u64 acc[4] = {0,0,0,0};
        const float* vrow = vt_s + dl*130;
        #pragma unroll 8
        for (int fq = 0; fq < 32; ++fq) {
            u64 w0 = *(const u64*)(vrow + fq*4);
            u64 w1 = *(const u64*)(vrow + fq*4 + 2);
            #pragma unroll
            for (int j = 0; j < 4; ++j) {
                ulonglong2 ev = *(const ulonglong2*)(eps_s + (n0+j)*128 + fq*4);
                ffma2(acc[j], w0, ev.x);
                ffma2(acc[j], w1, ev.y);
            }
        }
        #pragma unroll
        for (int j = 0; j < 4; ++j)
            atomicAdd(&g_v[(size_t)(n0+j)*Dn + d], hsum2(acc[j]));
    } else {
        // ---------------- app role ----------------
        float* cw_s = sm;              // 56 x 256 (rows >=49 zero)
        float* x_s  = sm + 56*256;     // 64 c x 64 p
        int r   = bx - 256;
        int b   = r / 48;
        int px0 = (r - b*48) * 64;
        for (int i = threadIdx.x; i < 56*256; i += 256) {
            int k = i >> 8, c = i & 255;
            cw_s[i] = (k < Kn) ? conv_w[k*Cn + c] : 0.0f;
        }
        int lane = threadIdx.x & 31;   // 2 px each
        int kg   = threadIdx.x >> 5;   // 8 groups x 7 k
        int k0   = kg * 7;
        u64 acc[7];
        #pragma unroll
        for (int kk = 0; kk < 7; ++kk) acc[kk] = 0;

        for (int c0 = 0; c0 < Cn; c0 += 64) {
            __syncthreads();
            for (int i = threadIdx.x; i < 64*64; i += 256) {
                int c = i >> 6, p = i & 63;
                x_s[i] = x[((size_t)b*Cn + c0 + c)*HWn + px0 + p];
            }
            __syncthreads();
            #pragma unroll 4
            for (int c = 0; c < 64; ++c) {
                u64 xv = *(const u64*)(x_s + c*64 + lane*2);
                #pragma unroll
                for (int kk = 0; kk < 7; ++kk) {
                    float w = cw_s[(k0+kk)*256 + c0 + c];
                    u64 w2; asm("mov.b64 %0, {%1, %1};" : "=l"(w2) : "f"(w));
                    ffma2(acc[kk], w2, xv);
                }
            }
        }
        int p0 = px0 + lane*2;
        #pragma unroll
        for (int kk = 0; kk < 7; ++kk) {
            int k = k0 + kk;
            if (k < Kn) {
                float bias = conv_b[k];
                float2 a0 = *(float2*)&acc[kk];
                float2 v;
                v.x = expf(a0.x + bias);
                v.y = expf(a0.y + bias);
                *(float2*)(g_eapp + ((size_t)b*Kn + k)*HWn + p0) = v;
            }
        }
    }
}

// ---------------- bvec partials: grid (196 ko-tiles, 4 d-slices), staged W ----
__global__ void k_bvec(const float* __restrict__ W_box) {
    extern __shared__ __align__(16) float smb[];
    float* v_s  = smb;            // [32 n][128 f]
    float* wt_s = smb + 32*128;   // [64 ko][130]
    int ks = blockIdx.y;
    int f0 = ks * 128;
    int ko0 = blockIdx.x * 64;
    for (int i = threadIdx.x; i < 32*128; i += 256) {
        int n = i >> 7, fl = i & 127;
        v_s[i] = g_v[n*Dn + f0 + fl];
    }
    int srow = threadIdx.x >> 5, scol = threadIdx.x & 31;
    #pragma unroll
    for (int p = 0; p < 8; ++p) {
        int row = p*8 + srow;
        float4 wv = *(const float4*)(W_box + (size_t)(ko0 + row)*Dn + f0 + scol*4);
        float* dst = wt_s + row*130 + scol*4;
        *(float2*)(dst)     = make_float2(wv.x, wv.y);
        *(float2*)(dst + 2) = make_float2(wv.z, wv.w);
    }
    __syncthreads();
    int kol = threadIdx.x & 63;
    int ng  = threadIdx.x >> 6;
    int n0  = ng * 8;
    int ko  = ko0 + kol;
    const float* wrow = wt_s + kol*130;
    u64 acc[8] = {0,0,0,0,0,0,0,0};
    #pragma unroll 4
    for (int fq = 0; fq < 32; ++fq) {
        u64 w0 = *(const u64*)(wrow + fq*4);
        u64 w1 = *(const u64*)(wrow + fq*4 + 2);
        #pragma unroll
        for (int j = 0; j < 8; ++j) {
            ulonglong2 vv = *(const ulonglong2*)(v_s + (n0+j)*128 + fq*4);
            ffma2(acc[j], w0, vv.x);
            ffma2(acc[j], w1, vv.y);
        }
    }
    #pragma unroll
    for (int j = 0; j < 8; ++j)
        g_bvp[(size_t)ks*(Nn*KOn) + (size_t)(n0+j)*KOn + ko] = hsum2(acc[j]);
}

// ---------------- eGA/eGB: grid (n, side, 7 k-groups); reduces bvec partials ----
__global__ void k_GAB() {
    extern __shared__ __align__(16) float sm[];
    float* bv_s = sm;         // 7*256
    float* M_s  = sm + 7*256; // 256*(L+1)
    int n  = blockIdx.x;
    bool isA = (blockIdx.y == 0);
    int kg = blockIdx.z;
    int k0 = kg * 7;
    int L  = isA ? Hn : Wn;
    int Lp = L + 1;
    const float* src = isA ? g_A : g_Bm;
    for (int i = threadIdx.x; i < 7*256; i += 256) {
        size_t base = (size_t)n*KOn + (size_t)k0*256 + i;
        float s = 0.f;
        #pragma unroll
        for (int p = 0; p < BSPLIT; ++p) s += g_bvp[(size_t)p*(Nn*KOn) + base];
        bv_s[i] = s;
    }
    for (int i = threadIdx.x; i < L*On; i += 256) {
        int l = i / On, o = i & 255;
        M_s[o*Lp + l] = src[i];
    }
    __syncthreads();
    float* dst = isA ? (g_eGA + n*Kn*Hn) : (g_eGB + n*Kn*Wn);
    if (isA) {
        for (int idx = threadIdx.x; idx < 7*Hn; idx += 256) {
            int kk = idx >> 6, l = idx & 63;
            const float4* bp = (const float4*)(bv_s + kk*256);
            float acc = 0.f;
            #pragma unroll 8
            for (int o4 = 0; o4 < 64; ++o4) {
                float4 bv = bp[o4];
                int ob = o4*4;
                acc += bv.x*M_s[ ob   *65 + l] + bv.y*M_s[(ob+1)*65 + l]
                     + bv.z*M_s[(ob+2)*65 + l] + bv.w*M_s[(ob+3)*65 + l];
            }
            dst[(k0+kk)*Hn + l] = expf(acc);
        }
    } else {
        for (int idx = threadIdx.x; idx < 7*Wn; idx += 256) {
            int kk = idx / 48, l = idx - kk*48;
            const float4* bp = (const float4*)(bv_s + kk*256);
            float acc = 0.f;
            #pragma unroll 8
            for (int o4 = 0; o4 < 64; ++o4) {
                float4 bv = bp[o4];
                int ob = o4*4;
                acc += bv.x*M_s[ ob   *49 + l] + bv.y*M_s[(ob+1)*49 + l]
                     + bv.z*M_s[(ob+2)*49 + l] + bv.w*M_s[(ob+3)*49 + l];
            }
            dst[(k0+kk)*Wn + l] = expf(acc);
        }
    }
}

// ---------------- final: softmax over k, permuted write (inline rank) ----------
__global__ void k_final(const float* __restrict__ rois, float* __restrict__ out) {
    __shared__ float eGA_s[Kn*Hn];
    __shared__ float eGB_s[Kn*Wn];
    __shared__ int r_s;
    int nb = blockIdx.y;
    int n = nb >> 2, b = nb & 3;
    if (threadIdx.x == 0) {
        int my = (int)rois[n*5];
        int r = 0;
        #pragma unroll
        for (int j = 0; j < Nn; ++j) {
            int o = (int)rois[j*5];
            r += (o < my) || (o == my && j < n);
        }
        r_s = r;
    }
    for (int i = threadIdx.x; i < Kn*Hn; i += 256) eGA_s[i] = g_eGA[n*Kn*Hn + i];
    for (int i = threadIdx.x; i < Kn*Wn; i += 256) eGB_s[i] = g_eGB[n*Kn*Wn + i];
    __syncthreads();
    int p = blockIdx.x*256 + threadIdx.x;
    int h = p / 48;
    int w = p - h*48;
    const float* ea = g_eapp + (size_t)b*Kn*HWn + p;
    float pr[Kn];
    float s = 0.f;
    #pragma unroll
    for (int k = 0; k < Kn; ++k) {
        pr[k] = eGA_s[k*Hn + h] * eGB_s[k*Wn + w] * ea[(size_t)k*HWn];
        s += pr[k];
    }
    float inv = 1.0f / s;
    float* op = out + ((size_t)(r_s*Bn + b)*Kn)*HWn + p;
    #pragma unroll
    for (int k = 0; k < Kn; ++k)
        op[(size_t)k*HWn] = pr[k] * inv;
}

extern "C" void kernel_launch(void* const* d_in, const int* in_sizes, int n_in,
                              void* d_out, int out_size) {
    const float* x      = (const float*)d_in[0];
    const float* rois   = (const float*)d_in[1];
    const float* V_box  = (const float*)d_in[2];
    const float* W_box  = (const float*)d_in[3];
    const float* W_im   = (const float*)d_in[4];
    const float* conv_w = (const float*)d_in[5];
    const float* conv_b = (const float*)d_in[6];
    float* out = (float*)d_out;

    int smem_vapp = (56*256 + 64*64) * 4;           // 73.7 KB (app role is max)
    int smem_bvec = (32*128 + 64*130) * 4;          // 49.7 KB
    int smem_gab  = (7*256 + 256*65) * 4;           // 73.7 KB
    cudaFuncSetAttribute(k_vapp, cudaFuncAttributeMaxDynamicSharedMemorySize, smem_vapp);
    cudaFuncSetAttribute(k_bvec, cudaFuncAttributeMaxDynamicSharedMemorySize, smem_bvec);
    cudaFuncSetAttribute(k_GAB,  cudaFuncAttributeMaxDynamicSharedMemorySize, smem_gab);

    k_pre  <<<Nn + Hn + Wn + 2, 256>>>(rois, W_im);
    k_vapp <<<256 + 192, 256, smem_vapp>>>(V_box, x, conv_w, conv_b);
    k_bvec <<<dim3(KOn/64, BSPLIT), 256, smem_bvec>>>(W_box);
    k_GAB  <<<dim3(Nn, 2, 7), 256, smem_gab>>>();
    k_final<<<dim3(HWn/256, Nn*Bn), 256>>>(rois, out);
}